// round 4
// baseline (speedup 1.0000x reference)
#include <cuda_runtime.h>

// ---------------------------------------------------------------------------
// O(2) FullTensorProduct — tile-grid formulation.
//
// Row layout identical to R3 kernel (verified correct, rel_err 3.3e-8).
// Change: instead of 1 CTA per batch row (2048 big CTAs -> 8.3% wave tail),
// decompose each row's 17920 float4 outputs into 35 uniform tiles of 512
// float4s. grid = (35, 2048), block = 512, one float4 store per thread,
// no SMEM, no __syncthreads. Inputs are read via __ldg (L2-hot, 5 MB set).
// ---------------------------------------------------------------------------

namespace {

constexpr int DIM1    = 448;
constexpr int ROW_OUT = 71680;           // floats per row
constexpr float R2f   = 0.70710678118654752440f;   // 1/sqrt(2)
constexpr float SQ2f  = 1.41421356237309504880f;   // sqrt(2)

// Tile kinds:
// 0 A  : (0)x(0)      scalar product
// 1 B  : (0)x(m)      sqrt2 * x1[u] * x2[2v+k]
// 2 C  : (m)x(0)      sqrt2 * x1[2u+k] * x2[v]
// 3 D+ : (m)x(m)->0+  R2*(c1 c2 + s1 s2)
// 4 D- : (m)x(m)->0-  R2*(s1 c2 - c1 s2)
// 5 Es : sum irrep    (c c2 - s s2,  s c2 + c s2)
// 6 E+ : diff, m1>m2  (c c2 + s s2,  s c2 - c s2)
// 7 E- : diff, m1<m2  (c c2 + s s2,  c s2 - s c2)
struct Tile { int out4; int x1o; int x2o; int code; int ib; };

__constant__ Tile g_tiles[35] = {
    // out4   x1o  x2o  code  ib
    {     0,    0,   0,  0,    0 },  // A   0x0 -> 0+
    {   512,   64,  32,  3,    0 },  // D+  1x1 -> 0+
    {  1024,  192,  96,  3,    0 },  // D+  2x2 -> 0+
    {  1536,   64,  32,  4,    0 },  // D-  1x1 -> 0-
    {  2048,  192,  96,  4,    0 },  // D-  2x2 -> 0-
    {  2560,    0,  32,  1,    0 },  // B   0x1 -> 1
    {  2560,    0,  32,  1,  512 },
    {  3584,   64,   0,  2,    0 },  // C   1x0 -> 1
    {  3584,   64,   0,  2,  512 },
    {  4608,   64,  96,  7,    0 },  // E-  1x2 -> 1
    {  4608,   64,  96,  7,  512 },
    {  5632,  192,  32,  6,    0 },  // E+  2x1 -> 1
    {  5632,  192,  32,  6,  512 },
    {  6656,  320,  96,  6,    0 },  // E+  3x2 -> 1
    {  6656,  320,  96,  6,  512 },
    {  7680,    0,  96,  1,    0 },  // B   0x2 -> 2
    {  7680,    0,  96,  1,  512 },
    {  8704,   64,  32,  5,    0 },  // Es  1x1 -> 2
    {  8704,   64,  32,  5,  512 },
    {  9728,  192,   0,  2,    0 },  // C   2x0 -> 2
    {  9728,  192,   0,  2,  512 },
    { 10752,  320,  32,  6,    0 },  // E+  3x1 -> 2
    { 10752,  320,  32,  6,  512 },
    { 11776,   64,  96,  5,    0 },  // Es  1x2 -> 3
    { 11776,   64,  96,  5,  512 },
    { 12800,  192,  32,  5,    0 },  // Es  2x1 -> 3
    { 12800,  192,  32,  5,  512 },
    { 13824,  320,   0,  2,    0 },  // C   3x0 -> 3
    { 13824,  320,   0,  2,  512 },
    { 14848,  192,  96,  5,    0 },  // Es  2x2 -> 4
    { 14848,  192,  96,  5,  512 },
    { 15872,  320,  32,  5,    0 },  // Es  3x1 -> 4
    { 15872,  320,  32,  5,  512 },
    { 16896,  320,  96,  5,    0 },  // Es  3x2 -> 5
    { 16896,  320,  96,  5,  512 },
};

__global__ void __launch_bounds__(512) tp_kernel(const float* __restrict__ in1,
                                                 const float* __restrict__ in2,
                                                 float* __restrict__ out) {
    const Tile tl = g_tiles[blockIdx.x];
    const size_t b = blockIdx.y;

    const float*  x1   = in1 + b * (size_t)DIM1 + tl.x1o;
    const float*  x2   = in2 + b * (size_t)160  + tl.x2o;
    const float2* x1v2 = reinterpret_cast<const float2*>(x1);
    const float2* x2v2 = reinterpret_cast<const float2*>(x2);
    const float4* x2v4 = reinterpret_cast<const float4*>(x2);

    float4* o = reinterpret_cast<float4*>(out + b * (size_t)ROW_OUT)
                + tl.out4 + tl.ib;

    const int t   = threadIdx.x;          // 0..511
    const int idx = tl.ib + t;            // element index within chunk

    float4 r;
    switch (tl.code) {
    case 0: {  // A: out[u*32+v] = x1[u]*x2[v]
        float  a = __ldg(x1 + (idx >> 3));
        float4 q = __ldg(x2v4 + (idx & 7));
        r = make_float4(a * q.x, a * q.y, a * q.z, a * q.w);
    } break;
    case 1: {  // B
        float  a = SQ2f * __ldg(x1 + (idx >> 4));
        float4 q = __ldg(x2v4 + (idx & 15));
        r = make_float4(a * q.x, a * q.y, a * q.z, a * q.w);
    } break;
    case 2: {  // C
        float2 ab = __ldg(x1v2 + (idx >> 4));
        float2 pq = __ldg(x2v2 + (idx & 15));
        r = make_float4(SQ2f * ab.x * pq.x, SQ2f * ab.y * pq.x,
                        SQ2f * ab.x * pq.y, SQ2f * ab.y * pq.y);
    } break;
    case 3: {  // D+ : R2*(c1*c2 + s1*s2), 4 consecutive v
        float2 cs = __ldg(x1v2 + (idx >> 3));
        int    j  = idx & 7;
        float4 a  = __ldg(x2v4 + 2 * j);
        float4 q  = __ldg(x2v4 + 2 * j + 1);
        r.x = R2f * fmaf(cs.x, a.x, cs.y * a.y);
        r.y = R2f * fmaf(cs.x, a.z, cs.y * a.w);
        r.z = R2f * fmaf(cs.x, q.x, cs.y * q.y);
        r.w = R2f * fmaf(cs.x, q.z, cs.y * q.w);
    } break;
    case 4: {  // D- : R2*(s1*c2 - c1*s2)
        float2 cs = __ldg(x1v2 + (idx >> 3));
        int    j  = idx & 7;
        float4 a  = __ldg(x2v4 + 2 * j);
        float4 q  = __ldg(x2v4 + 2 * j + 1);
        r.x = R2f * fmaf(cs.y, a.x, -(cs.x * a.y));
        r.y = R2f * fmaf(cs.y, a.z, -(cs.x * a.w));
        r.z = R2f * fmaf(cs.y, q.x, -(cs.x * q.y));
        r.w = R2f * fmaf(cs.y, q.z, -(cs.x * q.w));
    } break;
    case 5: {  // E sum: (c c2 - s s2, s c2 + c s2)
        float2 cs = __ldg(x1v2 + (idx >> 4));
        float4 q  = __ldg(x2v4 + (idx & 15));
        r.x = fmaf(cs.x, q.x, -(cs.y * q.y));
        r.y = fmaf(cs.y, q.x,   cs.x * q.y);
        r.z = fmaf(cs.x, q.z, -(cs.y * q.w));
        r.w = fmaf(cs.y, q.z,   cs.x * q.w);
    } break;
    case 6: {  // E diff sgn=+1: (c c2 + s s2, s c2 - c s2)
        float2 cs = __ldg(x1v2 + (idx >> 4));
        float4 q  = __ldg(x2v4 + (idx & 15));
        r.x = fmaf(cs.x, q.x,   cs.y * q.y);
        r.y = fmaf(cs.y, q.x, -(cs.x * q.y));
        r.z = fmaf(cs.x, q.z,   cs.y * q.w);
        r.w = fmaf(cs.y, q.z, -(cs.x * q.w));
    } break;
    default: {  // 7, E diff sgn=-1: (c c2 + s s2, c s2 - s c2)
        float2 cs = __ldg(x1v2 + (idx >> 4));
        float4 q  = __ldg(x2v4 + (idx & 15));
        r.x = fmaf(cs.x, q.x,   cs.y * q.y);
        r.y = fmaf(cs.x, q.y, -(cs.y * q.x));
        r.z = fmaf(cs.x, q.z,   cs.y * q.w);
        r.w = fmaf(cs.x, q.w, -(cs.y * q.z));
    } break;
    }

    __stcs(o + t, r);
}

} // namespace

extern "C" void kernel_launch(void* const* d_in, const int* in_sizes, int n_in,
                              void* d_out, int out_size) {
    const float* in1 = (const float*)d_in[0];   // (B, 448)
    const float* in2 = (const float*)d_in[1];   // (B, 160)
    float* out = (float*)d_out;                 // (B, 71680)
    const int batch = in_sizes[0] / DIM1;       // 2048
    dim3 grid(35, batch);
    tp_kernel<<<grid, 512>>>(in1, in2, out);
}

// round 5
// speedup vs baseline: 1.1431x; 1.1431x over previous
#include <cuda_runtime.h>

// ---------------------------------------------------------------------------
// O(2) FullTensorProduct — single-wave formulation.
//
// R3 structure (1 CTA per batch row, inputs staged in SMEM, long per-thread
// STG.128 streams) but with block=128 and __launch_bounds__(128,16):
// 16 CTAs/SM x 148 SMs = 2368 slots >= 2048 CTAs -> entire grid is ONE wave,
// eliminating R3's 8.3% wave-quantization tail. 140 float4 stores per thread.
// ---------------------------------------------------------------------------

namespace {

constexpr int DIM1    = 448;
constexpr int DIM2    = 160;
constexpr int ROW_OUT = 71680;
constexpr float R2f   = 0.70710678118654752440f;   // 1/sqrt(2)
constexpr float SQ2f  = 1.41421356237309504880f;   // sqrt(2)

__device__ __forceinline__ void st4(float* base, int idx4, float4 v) {
    __stcs(reinterpret_cast<float4*>(base) + idx4, v);
}

// kind A: (m=0)x(m=0) -> scalar. out[u*32+v] = x1[u]*x2[v].  512 float4.
__device__ __forceinline__ void chunkA(float* o, const float* x1, const float* x2, int t) {
#pragma unroll
    for (int it = 0; it < 4; ++it) {
        int idx = it * 128 + t;          // 0..511
        int u   = idx >> 3;
        int v   = (idx & 7) << 2;
        float a = x1[u];
        st4(o, idx, make_float4(a * x2[v], a * x2[v + 1], a * x2[v + 2], a * x2[v + 3]));
    }
}

// kind B: (m=0)x(m>0). 1024 float4.
__device__ __forceinline__ void chunkB(float* o, const float* x1, const float* x2, int t) {
#pragma unroll
    for (int it = 0; it < 8; ++it) {
        int idx = it * 128 + t;          // 0..1023
        int u   = idx >> 4;
        int j   = (idx & 15) << 2;
        float a = SQ2f * x1[u];
        st4(o, idx, make_float4(a * x2[j], a * x2[j + 1], a * x2[j + 2], a * x2[j + 3]));
    }
}

// kind C: (m>0)x(m=0). 1024 float4.
__device__ __forceinline__ void chunkC(float* o, const float* x1, const float* x2, int t) {
#pragma unroll
    for (int it = 0; it < 8; ++it) {
        int idx = it * 128 + t;
        int u   = idx >> 4;
        int j   = (idx & 15) << 1;
        float a = SQ2f * x1[2 * u];
        float b = SQ2f * x1[2 * u + 1];
        float p = x2[j], q = x2[j + 1];
        st4(o, idx, make_float4(a * p, b * p, a * q, b * q));
    }
}

// kind D: (m)x(m) -> m=0. 512 float4.
template<bool PLUS>
__device__ __forceinline__ void chunkD(float* o, const float* x1, const float* x2, int t) {
#pragma unroll
    for (int it = 0; it < 4; ++it) {
        int idx = it * 128 + t;
        int u   = idx >> 3;
        int j   = idx & 7;
        float c1 = x1[2 * u], s1 = x1[2 * u + 1];
        float r[4];
#pragma unroll
        for (int k = 0; k < 4; ++k) {
            float c2 = x2[8 * j + 2 * k];
            float s2 = x2[8 * j + 2 * k + 1];
            r[k] = PLUS ? R2f * fmaf(c1, c2,  s1 * s2)
                        : R2f * fmaf(s1, c2, -(c1 * s2));
        }
        st4(o, idx, make_float4(r[0], r[1], r[2], r[3]));
    }
}

// kind E: (m1)x(m2) -> 2-dim irrep. 1024 float4.
template<int SA, int SSC, int SCS>
__device__ __forceinline__ void chunkE(float* o, const float* x1, const float* x2, int t) {
#pragma unroll
    for (int it = 0; it < 8; ++it) {
        int idx = it * 128 + t;
        int u   = idx >> 4;
        int j   = idx & 15;
        float c1 = x1[2 * u], s1 = x1[2 * u + 1];
        float4 r;
        {
            float c2 = x2[4 * j], s2 = x2[4 * j + 1];
            r.x = fmaf(c1, c2, float(SA) * (s1 * s2));
            r.y = fmaf(float(SSC) * s1, c2, float(SCS) * (c1 * s2));
        }
        {
            float c2 = x2[4 * j + 2], s2 = x2[4 * j + 3];
            r.z = fmaf(c1, c2, float(SA) * (s1 * s2));
            r.w = fmaf(float(SSC) * s1, c2, float(SCS) * (c1 * s2));
        }
        st4(o, idx, r);
    }
}

__global__ void __launch_bounds__(128, 16) tp_kernel(const float* __restrict__ in1,
                                                     const float* __restrict__ in2,
                                                     float* __restrict__ out) {
    __shared__ __align__(16) float s1[DIM1];
    __shared__ __align__(16) float s2[DIM2];

    const int t = threadIdx.x;            // 0..127
    const size_t b = blockIdx.x;

    // Stage inputs with float4 loads: 448/4 = 112 <= 128, 160/4 = 40.
    const float4* r1 = reinterpret_cast<const float4*>(in1 + b * DIM1);
    const float4* r2 = reinterpret_cast<const float4*>(in2 + b * DIM2);
    if (t < 112) reinterpret_cast<float4*>(s1)[t] = r1[t];
    if (t < 40)  reinterpret_cast<float4*>(s2)[t] = r2[t];
    __syncthreads();

    float* o = out + b * (size_t)ROW_OUT;

    const float* x1m0 = s1;          // [0,64)
    const float* x1m1 = s1 + 64;     // [64,192)
    const float* x1m2 = s1 + 192;    // [192,320)
    const float* x1m3 = s1 + 320;    // [320,448)
    const float* x2m0 = s2;          // [0,32)
    const float* x2m1 = s2 + 32;     // [32,96)
    const float* x2m2 = s2 + 96;     // [96,160)

    // Output chunks in INV (irrep-sorted, stable) order; offsets in floats.
    chunkA           (o + 0,     x1m0, x2m0, t);   // 0x0 -> 0+
    chunkD<true >    (o + 2048,  x1m1, x2m1, t);   // 1x1 -> 0+
    chunkD<true >    (o + 4096,  x1m2, x2m2, t);   // 2x2 -> 0+
    chunkD<false>    (o + 6144,  x1m1, x2m1, t);   // 1x1 -> 0-
    chunkD<false>    (o + 8192,  x1m2, x2m2, t);   // 2x2 -> 0-
    chunkB           (o + 10240, x1m0, x2m1, t);   // 0x1 -> 1
    chunkC           (o + 14336, x1m1, x2m0, t);   // 1x0 -> 1
    chunkE< 1,-1, 1> (o + 18432, x1m1, x2m2, t);   // 1x2 -> 1 (diff, sgn=-1)
    chunkE< 1, 1,-1> (o + 22528, x1m2, x2m1, t);   // 2x1 -> 1 (diff, sgn=+1)
    chunkE< 1, 1,-1> (o + 26624, x1m3, x2m2, t);   // 3x2 -> 1 (diff, sgn=+1)
    chunkB           (o + 30720, x1m0, x2m2, t);   // 0x2 -> 2
    chunkE<-1, 1, 1> (o + 34816, x1m1, x2m1, t);   // 1x1 -> 2 (sum)
    chunkC           (o + 38912, x1m2, x2m0, t);   // 2x0 -> 2
    chunkE< 1, 1,-1> (o + 43008, x1m3, x2m1, t);   // 3x1 -> 2 (diff, sgn=+1)
    chunkE<-1, 1, 1> (o + 47104, x1m1, x2m2, t);   // 1x2 -> 3 (sum)
    chunkE<-1, 1, 1> (o + 51200, x1m2, x2m1, t);   // 2x1 -> 3 (sum)
    chunkC           (o + 55296, x1m3, x2m0, t);   // 3x0 -> 3
    chunkE<-1, 1, 1> (o + 59392, x1m2, x2m2, t);   // 2x2 -> 4 (sum)
    chunkE<-1, 1, 1> (o + 63488, x1m3, x2m1, t);   // 3x1 -> 4 (sum)
    chunkE<-1, 1, 1> (o + 67584, x1m3, x2m2, t);   // 3x2 -> 5 (sum)
}

} // namespace

extern "C" void kernel_launch(void* const* d_in, const int* in_sizes, int n_in,
                              void* d_out, int out_size) {
    const float* in1 = (const float*)d_in[0];   // (B, 448)
    const float* in2 = (const float*)d_in[1];   // (B, 160)
    float* out = (float*)d_out;                 // (B, 71680)
    const int batch = in_sizes[0] / DIM1;       // 2048
    tp_kernel<<<batch, 128>>>(in1, in2, out);
}

// round 6
// speedup vs baseline: 1.1616x; 1.0162x over previous
#include <cuda_runtime.h>

// ---------------------------------------------------------------------------
// O(2) FullTensorProduct — single-wave, 2 rows per CTA.
//
// R3 structure (256-thread CTAs, SMEM-staged inputs, long per-thread STG.128
// streams) with geometry fixed for one full wave:
//   __launch_bounds__(256, 8) -> <=32 regs -> 8 CTAs/SM -> 1184 slots.
//   grid = 1024 CTAs, each handles rows {2b, 2b+1} -> 1024 <= 1184: ONE wave.
// Eliminates R3's ceil(2.31)=3 wave quantization (~23% loss) while avoiding
// R5's many-tiny-CTA spread penalty.
// ---------------------------------------------------------------------------

namespace {

constexpr int DIM1    = 448;
constexpr int DIM2    = 160;
constexpr int ROW_OUT = 71680;
constexpr float R2f   = 0.70710678118654752440f;   // 1/sqrt(2)
constexpr float SQ2f  = 1.41421356237309504880f;   // sqrt(2)

__device__ __forceinline__ void st4(float* base, int idx4, float4 v) {
    __stcs(reinterpret_cast<float4*>(base) + idx4, v);
}

// kind A: (m=0)x(m=0) -> scalar. 512 float4.
__device__ __forceinline__ void chunkA(float* o, const float* x1, const float* x2, int t) {
#pragma unroll
    for (int it = 0; it < 2; ++it) {
        int idx = it * 256 + t;          // 0..511
        int u   = idx >> 3;
        int v   = (idx & 7) << 2;
        float a = x1[u];
        st4(o, idx, make_float4(a * x2[v], a * x2[v + 1], a * x2[v + 2], a * x2[v + 3]));
    }
}

// kind B: (m=0)x(m>0). 1024 float4.
__device__ __forceinline__ void chunkB(float* o, const float* x1, const float* x2, int t) {
#pragma unroll
    for (int it = 0; it < 4; ++it) {
        int idx = it * 256 + t;          // 0..1023
        int u   = idx >> 4;
        int j   = (idx & 15) << 2;
        float a = SQ2f * x1[u];
        st4(o, idx, make_float4(a * x2[j], a * x2[j + 1], a * x2[j + 2], a * x2[j + 3]));
    }
}

// kind C: (m>0)x(m=0). 1024 float4.
__device__ __forceinline__ void chunkC(float* o, const float* x1, const float* x2, int t) {
#pragma unroll
    for (int it = 0; it < 4; ++it) {
        int idx = it * 256 + t;
        int u   = idx >> 4;
        int j   = (idx & 15) << 1;
        float a = SQ2f * x1[2 * u];
        float b = SQ2f * x1[2 * u + 1];
        float p = x2[j], q = x2[j + 1];
        st4(o, idx, make_float4(a * p, b * p, a * q, b * q));
    }
}

// kind D: (m)x(m) -> m=0. 512 float4.
template<bool PLUS>
__device__ __forceinline__ void chunkD(float* o, const float* x1, const float* x2, int t) {
#pragma unroll
    for (int it = 0; it < 2; ++it) {
        int idx = it * 256 + t;
        int u   = idx >> 3;
        int j   = idx & 7;
        float c1 = x1[2 * u], s1 = x1[2 * u + 1];
        float r[4];
#pragma unroll
        for (int k = 0; k < 4; ++k) {
            float c2 = x2[8 * j + 2 * k];
            float s2 = x2[8 * j + 2 * k + 1];
            r[k] = PLUS ? R2f * fmaf(c1, c2,  s1 * s2)
                        : R2f * fmaf(s1, c2, -(c1 * s2));
        }
        st4(o, idx, make_float4(r[0], r[1], r[2], r[3]));
    }
}

// kind E: (m1)x(m2) -> 2-dim irrep. 1024 float4.
template<int SA, int SSC, int SCS>
__device__ __forceinline__ void chunkE(float* o, const float* x1, const float* x2, int t) {
#pragma unroll
    for (int it = 0; it < 4; ++it) {
        int idx = it * 256 + t;
        int u   = idx >> 4;
        int j   = idx & 15;
        float c1 = x1[2 * u], s1 = x1[2 * u + 1];
        float4 r;
        {
            float c2 = x2[4 * j], s2 = x2[4 * j + 1];
            r.x = fmaf(c1, c2, float(SA) * (s1 * s2));
            r.y = fmaf(float(SSC) * s1, c2, float(SCS) * (c1 * s2));
        }
        {
            float c2 = x2[4 * j + 2], s2 = x2[4 * j + 3];
            r.z = fmaf(c1, c2, float(SA) * (s1 * s2));
            r.w = fmaf(float(SSC) * s1, c2, float(SCS) * (c1 * s2));
        }
        st4(o, idx, r);
    }
}

__device__ __forceinline__ void process_row(float* o, const float* s1, const float* s2, int t) {
    const float* x1m0 = s1;          // [0,64)
    const float* x1m1 = s1 + 64;     // [64,192)
    const float* x1m2 = s1 + 192;    // [192,320)
    const float* x1m3 = s1 + 320;    // [320,448)
    const float* x2m0 = s2;          // [0,32)
    const float* x2m1 = s2 + 32;     // [32,96)
    const float* x2m2 = s2 + 96;     // [96,160)

    chunkA           (o + 0,     x1m0, x2m0, t);   // 0x0 -> 0+
    chunkD<true >    (o + 2048,  x1m1, x2m1, t);   // 1x1 -> 0+
    chunkD<true >    (o + 4096,  x1m2, x2m2, t);   // 2x2 -> 0+
    chunkD<false>    (o + 6144,  x1m1, x2m1, t);   // 1x1 -> 0-
    chunkD<false>    (o + 8192,  x1m2, x2m2, t);   // 2x2 -> 0-
    chunkB           (o + 10240, x1m0, x2m1, t);   // 0x1 -> 1
    chunkC           (o + 14336, x1m1, x2m0, t);   // 1x0 -> 1
    chunkE< 1,-1, 1> (o + 18432, x1m1, x2m2, t);   // 1x2 -> 1 (diff, sgn=-1)
    chunkE< 1, 1,-1> (o + 22528, x1m2, x2m1, t);   // 2x1 -> 1 (diff, sgn=+1)
    chunkE< 1, 1,-1> (o + 26624, x1m3, x2m2, t);   // 3x2 -> 1 (diff, sgn=+1)
    chunkB           (o + 30720, x1m0, x2m2, t);   // 0x2 -> 2
    chunkE<-1, 1, 1> (o + 34816, x1m1, x2m1, t);   // 1x1 -> 2 (sum)
    chunkC           (o + 38912, x1m2, x2m0, t);   // 2x0 -> 2
    chunkE< 1, 1,-1> (o + 43008, x1m3, x2m1, t);   // 3x1 -> 2 (diff, sgn=+1)
    chunkE<-1, 1, 1> (o + 47104, x1m1, x2m2, t);   // 1x2 -> 3 (sum)
    chunkE<-1, 1, 1> (o + 51200, x1m2, x2m1, t);   // 2x1 -> 3 (sum)
    chunkC           (o + 55296, x1m3, x2m0, t);   // 3x0 -> 3
    chunkE<-1, 1, 1> (o + 59392, x1m2, x2m2, t);   // 2x2 -> 4 (sum)
    chunkE<-1, 1, 1> (o + 63488, x1m3, x2m1, t);   // 3x1 -> 4 (sum)
    chunkE<-1, 1, 1> (o + 67584, x1m3, x2m2, t);   // 3x2 -> 5 (sum)
}

__global__ void __launch_bounds__(256, 8) tp_kernel(const float* __restrict__ in1,
                                                    const float* __restrict__ in2,
                                                    float* __restrict__ out) {
    __shared__ __align__(16) float s1[2 * DIM1];
    __shared__ __align__(16) float s2[2 * DIM2];

    const int t = threadIdx.x;            // 0..255
    const size_t b0 = (size_t)blockIdx.x * 2;   // first of two rows

    // Stage BOTH rows up front (rows are contiguous in gmem).
    // in1 pair: 896 floats = 224 float4; in2 pair: 320 floats = 80 float4.
    const float4* r1 = reinterpret_cast<const float4*>(in1 + b0 * DIM1);
    const float4* r2 = reinterpret_cast<const float4*>(in2 + b0 * DIM2);
    if (t < 224) reinterpret_cast<float4*>(s1)[t] = r1[t];
    if (t < 80)  reinterpret_cast<float4*>(s2)[t] = r2[t];
    __syncthreads();

    process_row(out +  b0      * (size_t)ROW_OUT, s1,        s2,        t);
    process_row(out + (b0 + 1) * (size_t)ROW_OUT, s1 + DIM1, s2 + DIM2, t);
}

} // namespace

extern "C" void kernel_launch(void* const* d_in, const int* in_sizes, int n_in,
                              void* d_out, int out_size) {
    const float* in1 = (const float*)d_in[0];   // (B, 448)
    const float* in2 = (const float*)d_in[1];   // (B, 160)
    float* out = (float*)d_out;                 // (B, 71680)
    const int batch = in_sizes[0] / DIM1;       // 2048
    tp_kernel<<<batch / 2, 256>>>(in1, in2, out);
}

// round 7
// speedup vs baseline: 1.3290x; 1.1441x over previous
#include <cuda_runtime.h>

// ---------------------------------------------------------------------------
// O(2) FullTensorProduct — half-row CTAs, backfill-friendly multi-wave.
//
// Evidence from R3/R5/R6: multi-wave + backfill beats single-wave (spread
// exposure); R3's loss was the 31%-full final wave. Here each batch row is
// split into two half-row CTAs (35 STG.128 per thread), grid = 4096, and
// __launch_bounds__(256,7) gives 7 CTAs/SM -> 1036 slots/wave ->
// 4096/1036 = 3.95 waves: final wave 95% full.
// ---------------------------------------------------------------------------

namespace {

constexpr int DIM1    = 448;
constexpr int DIM2    = 160;
constexpr int ROW_OUT = 71680;
constexpr float R2f   = 0.70710678118654752440f;   // 1/sqrt(2)
constexpr float SQ2f  = 1.41421356237309504880f;   // sqrt(2)

__device__ __forceinline__ void st4(float* base, int idx4, float4 v) {
    __stcs(reinterpret_cast<float4*>(base) + idx4, v);
}

// kind A: (m=0)x(m=0) -> scalar. 512 float4 total; this CTA does 256.
__device__ __forceinline__ void chunkA(float* o, const float* x1, const float* x2,
                                       int t, int h) {
    int idx = h * 256 + t;               // 0..511
    int u   = idx >> 3;
    int v   = (idx & 7) << 2;
    float a = x1[u];
    st4(o, idx, make_float4(a * x2[v], a * x2[v + 1], a * x2[v + 2], a * x2[v + 3]));
}

// kind B: (m=0)x(m>0). 1024 float4 total; this CTA does 512.
__device__ __forceinline__ void chunkB(float* o, const float* x1, const float* x2,
                                       int t, int h) {
#pragma unroll
    for (int it = 0; it < 2; ++it) {
        int idx = (h * 2 + it) * 256 + t;    // 0..1023
        int u   = idx >> 4;
        int j   = (idx & 15) << 2;
        float a = SQ2f * x1[u];
        st4(o, idx, make_float4(a * x2[j], a * x2[j + 1], a * x2[j + 2], a * x2[j + 3]));
    }
}

// kind C: (m>0)x(m=0). 1024 float4 total; this CTA does 512.
__device__ __forceinline__ void chunkC(float* o, const float* x1, const float* x2,
                                       int t, int h) {
#pragma unroll
    for (int it = 0; it < 2; ++it) {
        int idx = (h * 2 + it) * 256 + t;
        int u   = idx >> 4;
        int j   = (idx & 15) << 1;
        float a = SQ2f * x1[2 * u];
        float b = SQ2f * x1[2 * u + 1];
        float p = x2[j], q = x2[j + 1];
        st4(o, idx, make_float4(a * p, b * p, a * q, b * q));
    }
}

// kind D: (m)x(m) -> m=0. 512 float4 total; this CTA does 256.
template<bool PLUS>
__device__ __forceinline__ void chunkD(float* o, const float* x1, const float* x2,
                                       int t, int h) {
    int idx = h * 256 + t;
    int u   = idx >> 3;
    int j   = idx & 7;
    float c1 = x1[2 * u], s1 = x1[2 * u + 1];
    float r[4];
#pragma unroll
    for (int k = 0; k < 4; ++k) {
        float c2 = x2[8 * j + 2 * k];
        float s2 = x2[8 * j + 2 * k + 1];
        r[k] = PLUS ? R2f * fmaf(c1, c2,  s1 * s2)
                    : R2f * fmaf(s1, c2, -(c1 * s2));
    }
    st4(o, idx, make_float4(r[0], r[1], r[2], r[3]));
}

// kind E: (m1)x(m2) -> 2-dim irrep. 1024 float4 total; this CTA does 512.
template<int SA, int SSC, int SCS>
__device__ __forceinline__ void chunkE(float* o, const float* x1, const float* x2,
                                       int t, int h) {
#pragma unroll
    for (int it = 0; it < 2; ++it) {
        int idx = (h * 2 + it) * 256 + t;
        int u   = idx >> 4;
        int j   = idx & 15;
        float c1 = x1[2 * u], s1 = x1[2 * u + 1];
        float4 r;
        {
            float c2 = x2[4 * j], s2 = x2[4 * j + 1];
            r.x = fmaf(c1, c2, float(SA) * (s1 * s2));
            r.y = fmaf(float(SSC) * s1, c2, float(SCS) * (c1 * s2));
        }
        {
            float c2 = x2[4 * j + 2], s2 = x2[4 * j + 3];
            r.z = fmaf(c1, c2, float(SA) * (s1 * s2));
            r.w = fmaf(float(SSC) * s1, c2, float(SCS) * (c1 * s2));
        }
        st4(o, idx, r);
    }
}

__global__ void __launch_bounds__(256, 7) tp_kernel(const float* __restrict__ in1,
                                                    const float* __restrict__ in2,
                                                    float* __restrict__ out) {
    __shared__ __align__(16) float s1[DIM1];
    __shared__ __align__(16) float s2[DIM2];

    const int t = threadIdx.x;                 // 0..255
    const unsigned bid = blockIdx.x;           // 0..4095
    const size_t b = bid >> 1;                 // batch row
    const int    h = bid & 1;                  // which half of the row

    const float4* r1 = reinterpret_cast<const float4*>(in1 + b * DIM1);
    const float4* r2 = reinterpret_cast<const float4*>(in2 + b * DIM2);
    if (t < 112) reinterpret_cast<float4*>(s1)[t] = r1[t];
    if (t < 40)  reinterpret_cast<float4*>(s2)[t] = r2[t];
    __syncthreads();

    float* o = out + b * (size_t)ROW_OUT;

    const float* x1m0 = s1;          // [0,64)
    const float* x1m1 = s1 + 64;     // [64,192)
    const float* x1m2 = s1 + 192;    // [192,320)
    const float* x1m3 = s1 + 320;    // [320,448)
    const float* x2m0 = s2;          // [0,32)
    const float* x2m1 = s2 + 32;     // [32,96)
    const float* x2m2 = s2 + 96;     // [96,160)

    // Output chunks in INV (irrep-sorted, stable) order; offsets in floats.
    chunkA           (o + 0,     x1m0, x2m0, t, h);   // 0x0 -> 0+
    chunkD<true >    (o + 2048,  x1m1, x2m1, t, h);   // 1x1 -> 0+
    chunkD<true >    (o + 4096,  x1m2, x2m2, t, h);   // 2x2 -> 0+
    chunkD<false>    (o + 6144,  x1m1, x2m1, t, h);   // 1x1 -> 0-
    chunkD<false>    (o + 8192,  x1m2, x2m2, t, h);   // 2x2 -> 0-
    chunkB           (o + 10240, x1m0, x2m1, t, h);   // 0x1 -> 1
    chunkC           (o + 14336, x1m1, x2m0, t, h);   // 1x0 -> 1
    chunkE< 1,-1, 1> (o + 18432, x1m1, x2m2, t, h);   // 1x2 -> 1 (diff, sgn=-1)
    chunkE< 1, 1,-1> (o + 22528, x1m2, x2m1, t, h);   // 2x1 -> 1 (diff, sgn=+1)
    chunkE< 1, 1,-1> (o + 26624, x1m3, x2m2, t, h);   // 3x2 -> 1 (diff, sgn=+1)
    chunkB           (o + 30720, x1m0, x2m2, t, h);   // 0x2 -> 2
    chunkE<-1, 1, 1> (o + 34816, x1m1, x2m1, t, h);   // 1x1 -> 2 (sum)
    chunkC           (o + 38912, x1m2, x2m0, t, h);   // 2x0 -> 2
    chunkE< 1, 1,-1> (o + 43008, x1m3, x2m1, t, h);   // 3x1 -> 2 (diff, sgn=+1)
    chunkE<-1, 1, 1> (o + 47104, x1m1, x2m2, t, h);   // 1x2 -> 3 (sum)
    chunkE<-1, 1, 1> (o + 51200, x1m2, x2m1, t, h);   // 2x1 -> 3 (sum)
    chunkC           (o + 55296, x1m3, x2m0, t, h);   // 3x0 -> 3
    chunkE<-1, 1, 1> (o + 59392, x1m2, x2m2, t, h);   // 2x2 -> 4 (sum)
    chunkE<-1, 1, 1> (o + 63488, x1m3, x2m1, t, h);   // 3x1 -> 4 (sum)
    chunkE<-1, 1, 1> (o + 67584, x1m3, x2m2, t, h);   // 3x2 -> 5 (sum)
}

} // namespace

extern "C" void kernel_launch(void* const* d_in, const int* in_sizes, int n_in,
                              void* d_out, int out_size) {
    const float* in1 = (const float*)d_in[0];   // (B, 448)
    const float* in2 = (const float*)d_in[1];   // (B, 160)
    float* out = (float*)d_out;                 // (B, 71680)
    const int batch = in_sizes[0] / DIM1;       // 2048
    tp_kernel<<<batch * 2, 256>>>(in1, in2, out);
}

// round 8
// speedup vs baseline: 1.3320x; 1.0022x over previous
#include <cuda_runtime.h>

// ---------------------------------------------------------------------------
// O(2) FullTensorProduct — half-row CTAs, 8 CTAs/SM (full warp occupancy).
//
// R7 geometry (half-row quanta, grid 4096, 256 threads, SMEM-staged inputs,
// 35 STG.128/thread) with ONE change: __launch_bounds__(256, 8) -> 32 regs
// -> 8 CTAs/SM -> 64/64 warps resident. Tests whether R7's 23% DRAM idle is
// store-concurrency (more warps -> fewer queue-dry gaps) or a write-BW wall.
// ---------------------------------------------------------------------------

namespace {

constexpr int DIM1    = 448;
constexpr int DIM2    = 160;
constexpr int ROW_OUT = 71680;
constexpr float R2f   = 0.70710678118654752440f;   // 1/sqrt(2)
constexpr float SQ2f  = 1.41421356237309504880f;   // sqrt(2)

__device__ __forceinline__ void st4(float* base, int idx4, float4 v) {
    __stcs(reinterpret_cast<float4*>(base) + idx4, v);
}

// kind A: (m=0)x(m=0) -> scalar. 512 float4 total; this CTA does 256.
__device__ __forceinline__ void chunkA(float* o, const float* x1, const float* x2,
                                       int t, int h) {
    int idx = h * 256 + t;               // 0..511
    int u   = idx >> 3;
    int v   = (idx & 7) << 2;
    float a = x1[u];
    st4(o, idx, make_float4(a * x2[v], a * x2[v + 1], a * x2[v + 2], a * x2[v + 3]));
}

// kind B: (m=0)x(m>0). 1024 float4 total; this CTA does 512.
__device__ __forceinline__ void chunkB(float* o, const float* x1, const float* x2,
                                       int t, int h) {
#pragma unroll
    for (int it = 0; it < 2; ++it) {
        int idx = (h * 2 + it) * 256 + t;    // 0..1023
        int u   = idx >> 4;
        int j   = (idx & 15) << 2;
        float a = SQ2f * x1[u];
        st4(o, idx, make_float4(a * x2[j], a * x2[j + 1], a * x2[j + 2], a * x2[j + 3]));
    }
}

// kind C: (m>0)x(m=0). 1024 float4 total; this CTA does 512.
__device__ __forceinline__ void chunkC(float* o, const float* x1, const float* x2,
                                       int t, int h) {
#pragma unroll
    for (int it = 0; it < 2; ++it) {
        int idx = (h * 2 + it) * 256 + t;
        int u   = idx >> 4;
        int j   = (idx & 15) << 1;
        float a = SQ2f * x1[2 * u];
        float b = SQ2f * x1[2 * u + 1];
        float p = x2[j], q = x2[j + 1];
        st4(o, idx, make_float4(a * p, b * p, a * q, b * q));
    }
}

// kind D: (m)x(m) -> m=0. 512 float4 total; this CTA does 256.
template<bool PLUS>
__device__ __forceinline__ void chunkD(float* o, const float* x1, const float* x2,
                                       int t, int h) {
    int idx = h * 256 + t;
    int u   = idx >> 3;
    int j   = idx & 7;
    float c1 = x1[2 * u], s1 = x1[2 * u + 1];
    float r[4];
#pragma unroll
    for (int k = 0; k < 4; ++k) {
        float c2 = x2[8 * j + 2 * k];
        float s2 = x2[8 * j + 2 * k + 1];
        r[k] = PLUS ? R2f * fmaf(c1, c2,  s1 * s2)
                    : R2f * fmaf(s1, c2, -(c1 * s2));
    }
    st4(o, idx, make_float4(r[0], r[1], r[2], r[3]));
}

// kind E: (m1)x(m2) -> 2-dim irrep. 1024 float4 total; this CTA does 512.
template<int SA, int SSC, int SCS>
__device__ __forceinline__ void chunkE(float* o, const float* x1, const float* x2,
                                       int t, int h) {
#pragma unroll
    for (int it = 0; it < 2; ++it) {
        int idx = (h * 2 + it) * 256 + t;
        int u   = idx >> 4;
        int j   = idx & 15;
        float c1 = x1[2 * u], s1 = x1[2 * u + 1];
        float4 r;
        {
            float c2 = x2[4 * j], s2 = x2[4 * j + 1];
            r.x = fmaf(c1, c2, float(SA) * (s1 * s2));
            r.y = fmaf(float(SSC) * s1, c2, float(SCS) * (c1 * s2));
        }
        {
            float c2 = x2[4 * j + 2], s2 = x2[4 * j + 3];
            r.z = fmaf(c1, c2, float(SA) * (s1 * s2));
            r.w = fmaf(float(SSC) * s1, c2, float(SCS) * (c1 * s2));
        }
        st4(o, idx, r);
    }
}

__global__ void __launch_bounds__(256, 8) tp_kernel(const float* __restrict__ in1,
                                                    const float* __restrict__ in2,
                                                    float* __restrict__ out) {
    __shared__ __align__(16) float s1[DIM1];
    __shared__ __align__(16) float s2[DIM2];

    const int t = threadIdx.x;                 // 0..255
    const unsigned bid = blockIdx.x;           // 0..4095
    const size_t b = bid >> 1;                 // batch row
    const int    h = bid & 1;                  // which half of the row

    const float4* r1 = reinterpret_cast<const float4*>(in1 + b * DIM1);
    const float4* r2 = reinterpret_cast<const float4*>(in2 + b * DIM2);
    if (t < 112) reinterpret_cast<float4*>(s1)[t] = r1[t];
    if (t < 40)  reinterpret_cast<float4*>(s2)[t] = r2[t];
    __syncthreads();

    float* o = out + b * (size_t)ROW_OUT;

    const float* x1m0 = s1;          // [0,64)
    const float* x1m1 = s1 + 64;     // [64,192)
    const float* x1m2 = s1 + 192;    // [192,320)
    const float* x1m3 = s1 + 320;    // [320,448)
    const float* x2m0 = s2;          // [0,32)
    const float* x2m1 = s2 + 32;     // [32,96)
    const float* x2m2 = s2 + 96;     // [96,160)

    // Output chunks in INV (irrep-sorted, stable) order; offsets in floats.
    chunkA           (o + 0,     x1m0, x2m0, t, h);   // 0x0 -> 0+
    chunkD<true >    (o + 2048,  x1m1, x2m1, t, h);   // 1x1 -> 0+
    chunkD<true >    (o + 4096,  x1m2, x2m2, t, h);   // 2x2 -> 0+
    chunkD<false>    (o + 6144,  x1m1, x2m1, t, h);   // 1x1 -> 0-
    chunkD<false>    (o + 8192,  x1m2, x2m2, t, h);   // 2x2 -> 0-
    chunkB           (o + 10240, x1m0, x2m1, t, h);   // 0x1 -> 1
    chunkC           (o + 14336, x1m1, x2m0, t, h);   // 1x0 -> 1
    chunkE< 1,-1, 1> (o + 18432, x1m1, x2m2, t, h);   // 1x2 -> 1 (diff, sgn=-1)
    chunkE< 1, 1,-1> (o + 22528, x1m2, x2m1, t, h);   // 2x1 -> 1 (diff, sgn=+1)
    chunkE< 1, 1,-1> (o + 26624, x1m3, x2m2, t, h);   // 3x2 -> 1 (diff, sgn=+1)
    chunkB           (o + 30720, x1m0, x2m2, t, h);   // 0x2 -> 2
    chunkE<-1, 1, 1> (o + 34816, x1m1, x2m1, t, h);   // 1x1 -> 2 (sum)
    chunkC           (o + 38912, x1m2, x2m0, t, h);   // 2x0 -> 2
    chunkE< 1, 1,-1> (o + 43008, x1m3, x2m1, t, h);   // 3x1 -> 2 (diff, sgn=+1)
    chunkE<-1, 1, 1> (o + 47104, x1m1, x2m2, t, h);   // 1x2 -> 3 (sum)
    chunkE<-1, 1, 1> (o + 51200, x1m2, x2m1, t, h);   // 2x1 -> 3 (sum)
    chunkC           (o + 55296, x1m3, x2m0, t, h);   // 3x0 -> 3
    chunkE<-1, 1, 1> (o + 59392, x1m2, x2m2, t, h);   // 2x2 -> 4 (sum)
    chunkE<-1, 1, 1> (o + 63488, x1m3, x2m1, t, h);   // 3x1 -> 4 (sum)
    chunkE<-1, 1, 1> (o + 67584, x1m3, x2m2, t, h);   // 3x2 -> 5 (sum)
}

} // namespace

extern "C" void kernel_launch(void* const* d_in, const int* in_sizes, int n_in,
                              void* d_out, int out_size) {
    const float* in1 = (const float*)d_in[0];   // (B, 448)
    const float* in2 = (const float*)d_in[1];   // (B, 160)
    float* out = (float*)d_out;                 // (B, 71680)
    const int batch = in_sizes[0] / DIM1;       // 2048
    tp_kernel<<<batch * 2, 256>>>(in1, in2, out);
}